// round 16
// baseline (speedup 1.0000x reference)
#include <cuda_runtime.h>
#include <cuda_bf16.h>
#include <math.h>
#include <stdint.h>

// Problem constants
#define Bw   1024
#define Nt   64
#define Cc   256
#define Hh   8
#define Dd   32
#define NAa  16
#define HID  512
#define LOG100 4.6051701859880914f

#define K2   512   // hi(256) | lo(256) packed width
#define NCH  12    // 12 chunks of 64 cols = K'=768 (hi*hi x4, hi*lo x4, lo*hi x4)

// ---------------- scratch (device globals; no allocation allowed) ----------
__device__ __nv_bfloat16 g_a3_m[(size_t)Bw * Nt * K2];
__device__ __nv_bfloat16 g_a3_p[(size_t)Bw * Nt * K2];
__device__ __nv_bfloat16 g_al3_m[(size_t)Bw * NAa * K2];
__device__ __nv_bfloat16 g_al3_p[(size_t)Bw * NAa * K2];
__device__ __nv_bfloat16 g_w3_qkv_m[768 * K2];
__device__ __nv_bfloat16 g_w3_qkv_p[768 * K2];
__device__ __nv_bfloat16 g_w3_anc_m[256 * K2];
__device__ __nv_bfloat16 g_w3_anc_p[256 * K2];
__device__ __nv_bfloat16 g_w3_prj_m[256 * K2];
__device__ __nv_bfloat16 g_w3_prj_p[256 * K2];
__device__ __nv_bfloat16 g_att3_m[(size_t)Bw * Nt * K2];
__device__ __nv_bfloat16 g_att3_p[(size_t)Bw * Nt * K2];
__device__ float g_qkv_m[(size_t)Bw * Nt * 768];
__device__ float g_qkv_p[(size_t)Bw * Nt * 768];
__device__ float g_anc_m[(size_t)Bw * NAa * 256];
__device__ float g_anc_p[(size_t)Bw * NAa * 256];
__device__ float g_rpb[225 * Hh];
__device__ float g_bias_m[768];
__device__ float g_bias_p[768];

// ---------------- small helpers ------------------------------------------
__device__ __forceinline__ uint32_t su32(const void* p) {
    uint32_t a;
    asm("{ .reg .u64 t; cvta.to.shared.u64 t, %1; cvt.u32.u64 %0, t; }"
        : "=r"(a) : "l"(p));
    return a;
}

__device__ __forceinline__ void hilo_store(const float4 v,
                                           __nv_bfloat16* __restrict__ out,
                                           size_t r, int c4) {
    __nv_bfloat16 h0 = __float2bfloat16(v.x), h1 = __float2bfloat16(v.y);
    __nv_bfloat16 h2 = __float2bfloat16(v.z), h3 = __float2bfloat16(v.w);
    __nv_bfloat16 l0 = __float2bfloat16(v.x - __bfloat162float(h0));
    __nv_bfloat16 l1 = __float2bfloat16(v.y - __bfloat162float(h1));
    __nv_bfloat16 l2 = __float2bfloat16(v.z - __bfloat162float(h2));
    __nv_bfloat16 l3 = __float2bfloat16(v.w - __bfloat162float(h3));
    __nv_bfloat162* oh = (__nv_bfloat162*)(out + r * K2 + c4 * 4);
    oh[0] = __halves2bfloat162(h0, h1);
    oh[1] = __halves2bfloat162(h2, h3);
    __nv_bfloat162* ol = (__nv_bfloat162*)(out + r * K2 + 256 + c4 * 4);
    ol[0] = __halves2bfloat162(l0, l1);
    ol[1] = __halves2bfloat162(l2, l3);
}

// ---------------- fp32 -> bf16 hi/lo split: [rows,256] -> [rows,512] -------
__global__ void conv_hilo(const float* __restrict__ in,
                          __nv_bfloat16* __restrict__ out, int rows) {
    int i = blockIdx.x * blockDim.x + threadIdx.x;
    int total = rows * (Cc / 4);
    if (i >= total) return;
    hilo_store(((const float4*)in)[i], out, (size_t)(i >> 6), i & 63);
}

// ---------------- fused prep: conv(act) + conv(qkv weight) + bias ---------
__global__ void prep_stream(const float* __restrict__ act, int act_rows,
                            const float* __restrict__ wq,
                            const float* __restrict__ qb,
                            const float* __restrict__ vb,
                            __nv_bfloat16* __restrict__ a3,
                            __nv_bfloat16* __restrict__ w3,
                            float* __restrict__ bias) {
    int actBlocks = act_rows / 4;
    int b = blockIdx.x;
    int t = threadIdx.x;
    if (b < actBlocks) {
        int i = b * 256 + t;
        hilo_store(((const float4*)act)[i], a3, (size_t)(i >> 6), i & 63);
    } else if (b < actBlocks + 192) {
        int i = (b - actBlocks) * 256 + t;
        hilo_store(((const float4*)wq)[i], w3, (size_t)(i >> 6), i & 63);
    } else {
        int i = (b - actBlocks - 192) * 256 + t;
        if (i < 768)
            bias[i] = (i < Cc) ? qb[i] : ((i < 2 * Cc) ? 0.0f : vb[i - 2 * Cc]);
    }
}

// ---------------- mma.sync bf16x3 NT GEMM body (3-stage pipeline) ----------
__device__ __forceinline__ void gemm_body(
    const __nv_bfloat16* __restrict__ A3, const __nv_bfloat16* __restrict__ B3,
    const float* __restrict__ bias, float* __restrict__ C, int M, int Nc)
{
    extern __shared__ char dsm[];
    uint32_t sbase = (su32(dsm) + 1023) & ~1023u;

    int t    = threadIdx.x;
    int wid  = t >> 5;
    int lane = t & 31;
    int wm   = wid >> 2;   // 0..1 (64 rows each)
    int wn   = wid & 3;    // 0..3 (32 cols each)
    int bm   = blockIdx.y * 128;
    int bn   = blockIdx.x * 128;

    int lrow = t >> 1;           // 0..127
    int lseg = (t & 1) * 4;      // 4 x 16B segments each
    const char* arow = (const char*)(A3 + (size_t)(bm + lrow) * K2);
    const char* brow = (const char*)(B3 + (size_t)(bn + lrow) * K2);
    uint32_t swz_st  = ((uint32_t)(lrow & 7)) << 4;
    uint32_t dst_row = (uint32_t)lrow * 128;

    uint32_t swz   = ((uint32_t)(lane & 7)) << 4;
    uint32_t arowb = (uint32_t)(wm * 64 + (lane & 15)) * 128;
    uint32_t browb = 16384u + (uint32_t)(wn * 32 + (lane & 7) + ((lane >> 4) * 8)) * 128;
    uint32_t acol  = (uint32_t)((lane >> 4) * 16);
    uint32_t bcol  = (uint32_t)(((lane >> 3) & 1) * 16);
    uint32_t a_off[4], b_off[4];
#pragma unroll
    for (int kk = 0; kk < 4; kk++) {
        a_off[kk] = arowb + ((acol + (uint32_t)kk * 32) ^ swz);
        b_off[kk] = browb + ((bcol + (uint32_t)kk * 32) ^ swz);
    }

    float acc[16][4];
#pragma unroll
    for (int i = 0; i < 16; i++)
#pragma unroll
        for (int j = 0; j < 4; j++) acc[i][j] = 0.0f;

#define LOAD_CHUNK(c, stage) do {                                              \
        int ka = ((c) < 8) ? ((c) & 3) : ((c) - 4);                            \
        int kb = ((c) < 4) ? (c) : (((c) < 8) ? (c) : ((c) - 8));              \
        const char* asrc = arow + ka * 128 + lseg * 16;                        \
        const char* bsrc = brow + kb * 128 + lseg * 16;                        \
        uint32_t ad = sbase + (stage) * 32768 + dst_row;                       \
        uint32_t bd = ad + 16384;                                              \
        _Pragma("unroll")                                                      \
        for (int i = 0; i < 4; i++) {                                          \
            uint32_t so = (uint32_t)((lseg + i) * 16) ^ swz_st;                \
            asm volatile("cp.async.cg.shared.global [%0], [%1], 16;"           \
                         :: "r"(ad + so), "l"(asrc + i * 16) : "memory");      \
            asm volatile("cp.async.cg.shared.global [%0], [%1], 16;"           \
                         :: "r"(bd + so), "l"(bsrc + i * 16) : "memory");      \
        }                                                                      \
        asm volatile("cp.async.commit_group;" ::: "memory");                   \
    } while (0)

    LOAD_CHUNK(0, 0);
    LOAD_CHUNK(1, 1);

#pragma unroll
    for (int c = 0; c < NCH; c++) {
        if (c + 2 < NCH) {
            asm volatile("cp.async.wait_group 1;" ::: "memory");
            __syncthreads();
            LOAD_CHUNK(c + 2, (c + 2) % 3);
        } else {
            asm volatile("cp.async.wait_group 0;" ::: "memory");
            __syncthreads();
        }

        uint32_t stage_base = sbase + (uint32_t)((c % 3) * 32768);
#pragma unroll
        for (int kk = 0; kk < 4; kk++) {
            uint32_t af[4][4];
#pragma unroll
            for (int mi = 0; mi < 4; mi++) {
                asm volatile(
                    "ldmatrix.sync.aligned.m8n8.x4.shared.b16 {%0,%1,%2,%3}, [%4];"
                    : "=r"(af[mi][0]), "=r"(af[mi][1]),
                      "=r"(af[mi][2]), "=r"(af[mi][3])
                    : "r"(stage_base + a_off[kk] + mi * 2048));
            }
            uint32_t bf[4][2];
#pragma unroll
            for (int np = 0; np < 2; np++) {
                uint32_t r0, r1, r2, r3;
                asm volatile(
                    "ldmatrix.sync.aligned.m8n8.x4.shared.b16 {%0,%1,%2,%3}, [%4];"
                    : "=r"(r0), "=r"(r1), "=r"(r2), "=r"(r3)
                    : "r"(stage_base + b_off[kk] + np * 2048));
                bf[np * 2 + 0][0] = r0; bf[np * 2 + 0][1] = r1;
                bf[np * 2 + 1][0] = r2; bf[np * 2 + 1][1] = r3;
            }
#pragma unroll
            for (int mi = 0; mi < 4; mi++)
#pragma unroll
                for (int ni = 0; ni < 4; ni++) {
                    float* d = acc[mi * 4 + ni];
                    asm volatile(
                        "mma.sync.aligned.m16n8k16.row.col.f32.bf16.bf16.f32 "
                        "{%0,%1,%2,%3}, {%4,%5,%6,%7}, {%8,%9}, {%0,%1,%2,%3};"
                        : "+f"(d[0]), "+f"(d[1]), "+f"(d[2]), "+f"(d[3])
                        : "r"(af[mi][0]), "r"(af[mi][1]),
                          "r"(af[mi][2]), "r"(af[mi][3]),
                          "r"(bf[ni][0]), "r"(bf[ni][1]));
                }
        }
    }
#undef LOAD_CHUNK

#pragma unroll
    for (int mi = 0; mi < 4; mi++) {
#pragma unroll
        for (int ni = 0; ni < 4; ni++) {
            int r0 = bm + wm * 64 + mi * 16 + (lane >> 2);
            int c0 = bn + wn * 32 + ni * 8 + (lane & 3) * 2;
            float b0 = bias ? bias[c0] : 0.0f;
            float b1 = bias ? bias[c0 + 1] : 0.0f;
            float* d = acc[mi * 4 + ni];
            *(float2*)(C + (size_t)r0 * Nc + c0)
                = make_float2(d[0] + b0, d[1] + b1);
            *(float2*)(C + (size_t)(r0 + 8) * Nc + c0)
                = make_float2(d[2] + b0, d[3] + b1);
        }
    }
}

__global__ __launch_bounds__(256) void gemm_mma(
    const __nv_bfloat16* __restrict__ A3, const __nv_bfloat16* __restrict__ B3,
    const float* __restrict__ bias, float* __restrict__ C, int M, int Nc)
{
    gemm_body(A3, B3, bias, C, M, Nc);
}

// dual-stream variant: blockIdx.z selects the (A,B,bias,C) set
__global__ __launch_bounds__(256) void gemm_mma_dual(
    const __nv_bfloat16* __restrict__ A0, const __nv_bfloat16* __restrict__ B0,
    const float* __restrict__ bias0, float* __restrict__ C0,
    const __nv_bfloat16* __restrict__ A1, const __nv_bfloat16* __restrict__ B1,
    const float* __restrict__ bias1, float* __restrict__ C1,
    int M, int Nc)
{
    if (blockIdx.z == 0) gemm_body(A0, B0, bias0, C0, M, Nc);
    else                 gemm_body(A1, B1, bias1, C1, M, Nc);
}

// ---------------- CPB MLP: 2 -> 512 -> H, then 16*sigmoid -----------------
__global__ void cpb_kernel(const float* __restrict__ w1,
                           const float* __restrict__ b1,
                           const float* __restrict__ w2) {
    int e = blockIdx.x;
    int j = threadIdx.x;
    __shared__ float hid[HID];

    int a  = e / 15;
    int bb = e % 15;
    float r0 = (float)(a - 7) / 7.0f * 8.0f;
    float r1 = (float)(bb - 7) / 7.0f * 8.0f;
    const float inv_log2_8 = 1.0f / log2f(8.0f);
    float c0 = copysignf(log2f(fabsf(r0) + 1.0f) * inv_log2_8, r0);
    float c1 = copysignf(log2f(fabsf(r1) + 1.0f) * inv_log2_8, r1);

    hid[j] = fmaxf(c0 * w1[2 * j] + c1 * w1[2 * j + 1] + b1[j], 0.0f);
    __syncthreads();

    if (j < Hh) {
        float s = 0.0f;
        const float* w2r = w2 + (size_t)j * HID;
        for (int k = 0; k < HID; k++) s += hid[k] * w2r[k];
        g_rpb[e * Hh + j] = 16.0f / (1.0f + expf(-s));
    }
}

// ---------------- anchor attention, dual-stream, 128 threads --------------
// grid (B*H, 2): blockIdx.y selects stream (0=m: scale=ls, 1=p: scale=ls^2).
__global__ __launch_bounds__(128) void attn_dual(
    const float* __restrict__ qkv0, const float* __restrict__ anc0,
    const float* __restrict__ s0,   const float* __restrict__ ls0,
    __nv_bfloat16* __restrict__ o0,
    const float* __restrict__ qkv1, const float* __restrict__ anc1,
    const float* __restrict__ s1,   const float* __restrict__ ls1,
    __nv_bfloat16* __restrict__ o1)
{
    int strm = blockIdx.y;
    const float* qkv = strm ? qkv1 : qkv0;
    const float* anc = strm ? anc1 : anc0;
    const float* s   = strm ? s1   : s0;
    const float* lsp = strm ? ls1  : ls0;
    __nv_bfloat16* out3 = strm ? o1 : o0;
    int square = strm;

    int bh  = blockIdx.x;
    int b   = bh >> 3;
    int h   = bh & 7;
    int tid = threadIdx.x;
    int n   = tid >> 1;
    int g   = tid & 1;

    __shared__ __align__(16) float an_sh[NAa][Dd];
    __shared__ __align__(16) float sv_sh[Nt][Dd];
    __shared__ __align__(16) float a2_sh[Nt][NAa];
    __shared__ float att_sh[Nt][Nt + 1];
    __shared__ float rpb_sh[225];

    for (int i = tid; i < 225; i += 128) rpb_sh[i] = g_rpb[i * Hh + h];

    if (tid < NAa) {
        const float4* ap = (const float4*)(anc + ((size_t)(b * NAa + tid) * Cc + h * Dd));
        float ar[Dd];
        float ss = 0.0f;
#pragma unroll
        for (int d4 = 0; d4 < 8; d4++) {
            float4 av = ap[d4];
            ar[4*d4+0] = av.x; ar[4*d4+1] = av.y; ar[4*d4+2] = av.z; ar[4*d4+3] = av.w;
            ss += av.x*av.x + av.y*av.y + av.z*av.z + av.w*av.w;
        }
        float inv = 1.0f / fmaxf(sqrtf(ss), 1e-12f);
#pragma unroll
        for (int d = 0; d < Dd; d++) an_sh[tid][d] = ar[d] * inv;
    }

    const float4* q4 = (const float4*)(qkv + ((size_t)(b * Nt + n) * 768 + h * Dd + g * 16));
    const float4* k4 = q4 + 64;
    const float4* v4 = q4 + 128;
    const float4* s4 = (const float4*)(s + ((size_t)(b * Nt + n) * Cc + h * Dd + g * 16));
    float qr[16], kr[16];
    float qs = 0.0f, ks = 0.0f;
#pragma unroll
    for (int d4 = 0; d4 < 4; d4++) {
        float4 qv = q4[d4], kv = k4[d4], vv = v4[d4], sv = s4[d4];
        qr[4*d4+0] = qv.x; qr[4*d4+1] = qv.y; qr[4*d4+2] = qv.z; qr[4*d4+3] = qv.w;
        kr[4*d4+0] = kv.x; kr[4*d4+1] = kv.y; kr[4*d4+2] = kv.z; kr[4*d4+3] = kv.w;
        qs += qv.x*qv.x + qv.y*qv.y + qv.z*qv.z + qv.w*qv.w;
        ks += kv.x*kv.x + kv.y*kv.y + kv.z*kv.z + kv.w*kv.w;
        sv_sh[n][g*16 + 4*d4+0] = vv.x * sv.x;
        sv_sh[n][g*16 + 4*d4+1] = vv.y * sv.y;
        sv_sh[n][g*16 + 4*d4+2] = vv.z * sv.z;
        sv_sh[n][g*16 + 4*d4+3] = vv.w * sv.w;
    }
    qs += __shfl_xor_sync(0xFFFFFFFFu, qs, 1);
    ks += __shfl_xor_sync(0xFFFFFFFFu, ks, 1);
    float qin = 1.0f / fmaxf(sqrtf(qs), 1e-12f);
    float kin = 1.0f / fmaxf(sqrtf(ks), 1e-12f);
    __syncthreads();

    float a1[NAa];
    float s1v = 0.0f, s2v = 0.0f;
    float a2f[NAa];
#pragma unroll
    for (int m = 0; m < NAa; m++) {
        float p1 = 0.0f, p2 = 0.0f;
#pragma unroll
        for (int d = 0; d < 16; d++) {
            float av = an_sh[m][g*16 + d];
            p1 += qr[d] * av;
            p2 += kr[d] * av;
        }
        p1 += __shfl_xor_sync(0xFFFFFFFFu, p1, 1);
        p2 += __shfl_xor_sync(0xFFFFFFFFu, p2, 1);
        p1 *= qin; p2 *= kin;
        a1[m] = p1; a2f[m] = p2;
        s1v += p1 * p1; s2v += p2 * p2;
    }
    float i1n = 1.0f / fmaxf(sqrtf(s1v), 1e-12f);
    float i2n = 1.0f / fmaxf(sqrtf(s2v), 1e-12f);
#pragma unroll
    for (int m = 0; m < NAa; m++) a1[m] *= i1n;
    if (g == 0) {
#pragma unroll
        for (int m = 0; m < NAa; m++) a2_sh[n][m] = a2f[m] * i2n;
    }
    __syncthreads();

    float lsv = expf(fminf(lsp[h], LOG100));
    float scale = square ? (lsv * lsv) : lsv;
    int i1 = n >> 3, j1 = n & 7;
    float lv[32];
    float mx = -1e30f;
#pragma unroll
    for (int j = 0; j < 32; j++) {
        int k2 = g * 32 + j;
        const float4* a2v = (const float4*)(&a2_sh[k2][0]);
        float4 v0 = a2v[0], v1 = a2v[1], v2 = a2v[2], v3 = a2v[3];
        float accv = a1[0]*v0.x + a1[1]*v0.y + a1[2]*v0.z + a1[3]*v0.w
                   + a1[4]*v1.x + a1[5]*v1.y + a1[6]*v1.z + a1[7]*v1.w
                   + a1[8]*v2.x + a1[9]*v2.y + a1[10]*v2.z + a1[11]*v2.w
                   + a1[12]*v3.x + a1[13]*v3.y + a1[14]*v3.z + a1[15]*v3.w;
        int idx = (i1 - (k2 >> 3) + 7) * 15 + (j1 - (k2 & 7) + 7);
        float v = accv * scale + rpb_sh[idx];
        lv[j] = v;
        mx = fmaxf(mx, v);
    }
    mx = fmaxf(mx, __shfl_xor_sync(0xFFFFFFFFu, mx, 1));
    float sum = 0.0f;
#pragma unroll
    for (int j = 0; j < 32; j++) {
        float e = __expf(lv[j] - mx);
        att_sh[n][g * 32 + j] = e;
        sum += e;
    }
    sum += __shfl_xor_sync(0xFFFFFFFFu, sum, 1);
    float rinv = 1.0f / sum;
    __syncthreads();

    float oa[16];
#pragma unroll
    for (int d = 0; d < 16; d++) oa[d] = 0.0f;
    for (int k2 = 0; k2 < Nt; k2++) {
        float a = att_sh[n][k2];
        const float4* svp = (const float4*)&sv_sh[k2][g * 16];
#pragma unroll
        for (int d4 = 0; d4 < 4; d4++) {
            float4 v = svp[d4];
            oa[4*d4+0] += a * v.x;
            oa[4*d4+1] += a * v.y;
            oa[4*d4+2] += a * v.z;
            oa[4*d4+3] += a * v.w;
        }
    }
    __nv_bfloat16* orow = out3 + ((size_t)(b * Nt + n) * K2 + h * Dd + g * 16);
#pragma unroll
    for (int d = 0; d < 16; d += 2) {
        float o0v = oa[d] * rinv;
        float o1v = oa[d + 1] * rinv;
        __nv_bfloat16 h0 = __float2bfloat16(o0v);
        __nv_bfloat16 h1 = __float2bfloat16(o1v);
        __nv_bfloat16 l0 = __float2bfloat16(o0v - __bfloat162float(h0));
        __nv_bfloat16 l1 = __float2bfloat16(o1v - __bfloat162float(h1));
        *(__nv_bfloat162*)(orow + d)       = __halves2bfloat162(h0, h1);
        *(__nv_bfloat162*)(orow + 256 + d) = __halves2bfloat162(l0, l1);
    }
}

// ---------------- launch --------------------------------------------------
extern "C" void kernel_launch(void* const* d_in, const int* in_sizes, int n_in,
                              void* d_out, int out_size) {
    const float* m        = (const float*)d_in[0];
    const float* p        = (const float*)d_in[1];
    const float* m_l      = (const float*)d_in[2];
    const float* m_s      = (const float*)d_in[3];
    const float* p_l      = (const float*)d_in[4];
    const float* p_s      = (const float*)d_in[5];
    const float* m_qkv_w  = (const float*)d_in[6];
    const float* p_qkv_w  = (const float*)d_in[7];
    const float* m_q_bias = (const float*)d_in[8];
    const float* m_v_bias = (const float*)d_in[9];
    const float* p_q_bias = (const float*)d_in[10];
    const float* p_v_bias = (const float*)d_in[11];
    const float* m_ls     = (const float*)d_in[12];
    const float* p_ls     = (const float*)d_in[13];
    const float* cpb_w1   = (const float*)d_in[14];
    const float* cpb_b1   = (const float*)d_in[15];
    const float* cpb_w2   = (const float*)d_in[16];
    const float* m_anchor_w = (const float*)d_in[17];
    const float* p_anchor_w = (const float*)d_in[18];
    const float* m_proj_w = (const float*)d_in[19];
    const float* m_proj_b = (const float*)d_in[20];
    const float* p_proj_w = (const float*)d_in[21];
    const float* p_proj_b = (const float*)d_in[22];
    float* out = (float*)d_out;

    __nv_bfloat16 *a3m, *a3p, *al3m, *al3p, *w3qm, *w3qp, *w3am, *w3ap, *w3pm, *w3pp, *at3m, *at3p;
    float *qkvm, *qkvp, *ancm, *ancp, *biasm, *biasp;
    cudaGetSymbolAddress((void**)&a3m,  g_a3_m);
    cudaGetSymbolAddress((void**)&a3p,  g_a3_p);
    cudaGetSymbolAddress((void**)&al3m, g_al3_m);
    cudaGetSymbolAddress((void**)&al3p, g_al3_p);
    cudaGetSymbolAddress((void**)&w3qm, g_w3_qkv_m);
    cudaGetSymbolAddress((void**)&w3qp, g_w3_qkv_p);
    cudaGetSymbolAddress((void**)&w3am, g_w3_anc_m);
    cudaGetSymbolAddress((void**)&w3ap, g_w3_anc_p);
    cudaGetSymbolAddress((void**)&w3pm, g_w3_prj_m);
    cudaGetSymbolAddress((void**)&w3pp, g_w3_prj_p);
    cudaGetSymbolAddress((void**)&at3m, g_att3_m);
    cudaGetSymbolAddress((void**)&at3p, g_att3_p);
    cudaGetSymbolAddress((void**)&qkvm, g_qkv_m);
    cudaGetSymbolAddress((void**)&qkvp, g_qkv_p);
    cudaGetSymbolAddress((void**)&ancm, g_anc_m);
    cudaGetSymbolAddress((void**)&ancp, g_anc_p);
    cudaGetSymbolAddress((void**)&biasm, g_bias_m);
    cudaGetSymbolAddress((void**)&biasp, g_bias_p);

    const int SMEMSZ = 3 * 32768 + 1024;
    cudaFuncSetAttribute(gemm_mma, cudaFuncAttributeMaxDynamicSharedMemorySize, SMEMSZ);
    cudaFuncSetAttribute(gemm_mma_dual, cudaFuncAttributeMaxDynamicSharedMemorySize, SMEMSZ);

    int MB = Bw * Nt;      // 65536
    int MA = Bw * NAa;     // 16384

    // launch 0: fused prep m; launch 1: QKV GEMM m (ncu capture target)
    prep_stream<<<MB / 4 + 192 + 3, 256>>>(m, MB, m_qkv_w, m_q_bias, m_v_bias,
                                           a3m, w3qm, biasm);
    gemm_mma<<<dim3(6, MB / 128), 256, SMEMSZ>>>(a3m, w3qm, biasm, qkvm, MB, 768);

    prep_stream<<<MB / 4 + 192 + 3, 256>>>(p, MB, p_qkv_w, p_q_bias, p_v_bias,
                                           a3p, w3qp, biasp);
    gemm_mma<<<dim3(6, MB / 128), 256, SMEMSZ>>>(a3p, w3qp, biasp, qkvp, MB, 768);

    conv_hilo<<<(MA * 64 + 255) / 256, 256>>>(m_l, al3m, MA);
    conv_hilo<<<(256 * 64 + 255) / 256, 256>>>(m_anchor_w, w3am, 256);
    conv_hilo<<<(MA * 64 + 255) / 256, 256>>>(p_l, al3p, MA);
    conv_hilo<<<(256 * 64 + 255) / 256, 256>>>(p_anchor_w, w3ap, 256);
    gemm_mma_dual<<<dim3(2, MA / 128, 2), 256, SMEMSZ>>>(
        al3m, w3am, nullptr, ancm, al3p, w3ap, nullptr, ancp, MA, 256);

    cpb_kernel<<<225, 512>>>(cpb_w1, cpb_b1, cpb_w2);

    attn_dual<<<dim3(Bw * Hh, 2), 128>>>(qkvm, ancm, m_s, m_ls, at3m,
                                         qkvp, ancp, p_s, p_ls, at3p);

    conv_hilo<<<(256 * 64 + 255) / 256, 256>>>(m_proj_w, w3pm, 256);
    conv_hilo<<<(256 * 64 + 255) / 256, 256>>>(p_proj_w, w3pp, 256);

    gemm_mma_dual<<<dim3(2, MB / 128, 2), 256, SMEMSZ>>>(
        at3m, w3pm, m_proj_b, out,
        at3p, w3pp, p_proj_b, out + (size_t)MB * Cc, MB, 256);
}

// round 17
// speedup vs baseline: 1.0203x; 1.0203x over previous
#include <cuda_runtime.h>
#include <cuda_bf16.h>
#include <math.h>
#include <stdint.h>

// Problem constants
#define Bw   1024
#define Nt   64
#define Cc   256
#define Hh   8
#define Dd   32
#define NAa  16
#define HID  512
#define LOG100 4.6051701859880914f

#define K2   512   // hi(256) | lo(256) packed width
#define NCH  12    // 12 chunks of 64 cols = K'=768 (hi*hi x4, hi*lo x4, lo*hi x4)

// ---------------- scratch (device globals; no allocation allowed) ----------
__device__ __nv_bfloat16 g_a3_m[(size_t)Bw * Nt * K2];
__device__ __nv_bfloat16 g_a3_p[(size_t)Bw * Nt * K2];
__device__ __nv_bfloat16 g_al3_m[(size_t)Bw * NAa * K2];
__device__ __nv_bfloat16 g_al3_p[(size_t)Bw * NAa * K2];
__device__ __nv_bfloat16 g_w3_qkv_m[768 * K2];
__device__ __nv_bfloat16 g_w3_qkv_p[768 * K2];
__device__ __nv_bfloat16 g_w3_anc_m[256 * K2];
__device__ __nv_bfloat16 g_w3_anc_p[256 * K2];
__device__ __nv_bfloat16 g_w3_prj_m[256 * K2];
__device__ __nv_bfloat16 g_w3_prj_p[256 * K2];
__device__ __nv_bfloat16 g_att3_m[(size_t)Bw * Nt * K2];
__device__ __nv_bfloat16 g_att3_p[(size_t)Bw * Nt * K2];
__device__ float g_qkv_m[(size_t)Bw * Nt * 768];
__device__ float g_qkv_p[(size_t)Bw * Nt * 768];
__device__ float g_anc_m[(size_t)Bw * NAa * 256];
__device__ float g_anc_p[(size_t)Bw * NAa * 256];
__device__ float g_rpb[225 * Hh];
__device__ float g_bias_m[768];
__device__ float g_bias_p[768];

// ---------------- small helpers ------------------------------------------
__device__ __forceinline__ uint32_t su32(const void* p) {
    uint32_t a;
    asm("{ .reg .u64 t; cvta.to.shared.u64 t, %1; cvt.u32.u64 %0, t; }"
        : "=r"(a) : "l"(p));
    return a;
}

__device__ __forceinline__ void hilo_store(const float4 v,
                                           __nv_bfloat16* __restrict__ out,
                                           size_t r, int c4) {
    __nv_bfloat16 h0 = __float2bfloat16(v.x), h1 = __float2bfloat16(v.y);
    __nv_bfloat16 h2 = __float2bfloat16(v.z), h3 = __float2bfloat16(v.w);
    __nv_bfloat16 l0 = __float2bfloat16(v.x - __bfloat162float(h0));
    __nv_bfloat16 l1 = __float2bfloat16(v.y - __bfloat162float(h1));
    __nv_bfloat16 l2 = __float2bfloat16(v.z - __bfloat162float(h2));
    __nv_bfloat16 l3 = __float2bfloat16(v.w - __bfloat162float(h3));
    __nv_bfloat162* oh = (__nv_bfloat162*)(out + r * K2 + c4 * 4);
    oh[0] = __halves2bfloat162(h0, h1);
    oh[1] = __halves2bfloat162(h2, h3);
    __nv_bfloat162* ol = (__nv_bfloat162*)(out + r * K2 + 256 + c4 * 4);
    ol[0] = __halves2bfloat162(l0, l1);
    ol[1] = __halves2bfloat162(l2, l3);
}

// ---------------- fused per-stream prep ------------------------------------
// block ranges:
//  [0, AB)            act conv (MB rows)
//  [AB, +192)         qkv weight conv (768 rows)
//  [AB+192, +3)       bias = concat(qb, 0, vb)
//  [AB+195, +4096)    anchor act conv (MA rows)
//  [AB+4291, +64)     anchor weight conv (256 rows)
//  [AB+4355, +225)    CPB MLP (only when cpb_w1 != nullptr)
#define AB (Bw * Nt / 4)   // 16384
__global__ void prep_full(const float* __restrict__ act,
                          const float* __restrict__ wq,
                          const float* __restrict__ qb,
                          const float* __restrict__ vb,
                          const float* __restrict__ al,
                          const float* __restrict__ wa,
                          __nv_bfloat16* __restrict__ a3,
                          __nv_bfloat16* __restrict__ w3,
                          float* __restrict__ bias,
                          __nv_bfloat16* __restrict__ al3,
                          __nv_bfloat16* __restrict__ w3a,
                          const float* __restrict__ cpb_w1,
                          const float* __restrict__ cpb_b1,
                          const float* __restrict__ cpb_w2) {
    int b = blockIdx.x;
    int t = threadIdx.x;
    if (b < AB) {
        int i = b * 256 + t;
        hilo_store(((const float4*)act)[i], a3, (size_t)(i >> 6), i & 63);
    } else if (b < AB + 192) {
        int i = (b - AB) * 256 + t;
        hilo_store(((const float4*)wq)[i], w3, (size_t)(i >> 6), i & 63);
    } else if (b < AB + 195) {
        int i = (b - AB - 192) * 256 + t;
        if (i < 768)
            bias[i] = (i < Cc) ? qb[i] : ((i < 2 * Cc) ? 0.0f : vb[i - 2 * Cc]);
    } else if (b < AB + 195 + 4096) {
        int i = (b - AB - 195) * 256 + t;
        hilo_store(((const float4*)al)[i], al3, (size_t)(i >> 6), i & 63);
    } else if (b < AB + 195 + 4096 + 64) {
        int i = (b - AB - 195 - 4096) * 256 + t;
        hilo_store(((const float4*)wa)[i], w3a, (size_t)(i >> 6), i & 63);
    } else if (cpb_w1 != nullptr) {
        // CPB MLP: 2 -> 512 -> H, 16*sigmoid. 256 threads, e = table entry.
        int e = b - (AB + 195 + 4096 + 64);
        __shared__ float hid[HID];
        int a  = e / 15;
        int bb = e % 15;
        float r0 = (float)(a - 7) / 7.0f * 8.0f;
        float r1 = (float)(bb - 7) / 7.0f * 8.0f;
        const float inv_log2_8 = 1.0f / log2f(8.0f);
        float c0 = copysignf(log2f(fabsf(r0) + 1.0f) * inv_log2_8, r0);
        float c1 = copysignf(log2f(fabsf(r1) + 1.0f) * inv_log2_8, r1);
#pragma unroll
        for (int j = t; j < HID; j += 256)
            hid[j] = fmaxf(c0 * cpb_w1[2 * j] + c1 * cpb_w1[2 * j + 1] + cpb_b1[j], 0.0f);
        __syncthreads();
        if (t < Hh) {
            float s = 0.0f;
            const float* w2r = cpb_w2 + (size_t)t * HID;
            for (int k = 0; k < HID; k++) s += hid[k] * w2r[k];
            g_rpb[e * Hh + t] = 16.0f / (1.0f + expf(-s));
        }
    }
}

// dual proj-weight conv: blocks 0-63 -> m, 64-127 -> p
__global__ void conv_proj_dual(const float* __restrict__ wm,
                               const float* __restrict__ wp,
                               __nv_bfloat16* __restrict__ o3m,
                               __nv_bfloat16* __restrict__ o3p) {
    int b = blockIdx.x;
    int t = threadIdx.x;
    if (b < 64) {
        int i = b * 256 + t;
        hilo_store(((const float4*)wm)[i], o3m, (size_t)(i >> 6), i & 63);
    } else {
        int i = (b - 64) * 256 + t;
        hilo_store(((const float4*)wp)[i], o3p, (size_t)(i >> 6), i & 63);
    }
}

// ---------------- mma.sync bf16x3 NT GEMM (3-stage pipeline, R15) ----------
__global__ __launch_bounds__(256) void gemm_mma(
    const __nv_bfloat16* __restrict__ A3, const __nv_bfloat16* __restrict__ B3,
    const float* __restrict__ bias, float* __restrict__ C, int M, int Nc)
{
    extern __shared__ char dsm[];
    uint32_t sbase = (su32(dsm) + 1023) & ~1023u;

    int t    = threadIdx.x;
    int wid  = t >> 5;
    int lane = t & 31;
    int wm   = wid >> 2;
    int wn   = wid & 3;
    int bm   = blockIdx.y * 128;
    int bn   = blockIdx.x * 128;

    int lrow = t >> 1;
    int lseg = (t & 1) * 4;
    const char* arow = (const char*)(A3 + (size_t)(bm + lrow) * K2);
    const char* brow = (const char*)(B3 + (size_t)(bn + lrow) * K2);
    uint32_t swz_st  = ((uint32_t)(lrow & 7)) << 4;
    uint32_t dst_row = (uint32_t)lrow * 128;

    uint32_t swz   = ((uint32_t)(lane & 7)) << 4;
    uint32_t arowb = (uint32_t)(wm * 64 + (lane & 15)) * 128;
    uint32_t browb = 16384u + (uint32_t)(wn * 32 + (lane & 7) + ((lane >> 4) * 8)) * 128;
    uint32_t acol  = (uint32_t)((lane >> 4) * 16);
    uint32_t bcol  = (uint32_t)(((lane >> 3) & 1) * 16);
    uint32_t a_off[4], b_off[4];
#pragma unroll
    for (int kk = 0; kk < 4; kk++) {
        a_off[kk] = arowb + ((acol + (uint32_t)kk * 32) ^ swz);
        b_off[kk] = browb + ((bcol + (uint32_t)kk * 32) ^ swz);
    }

    float acc[16][4];
#pragma unroll
    for (int i = 0; i < 16; i++)
#pragma unroll
        for (int j = 0; j < 4; j++) acc[i][j] = 0.0f;

#define LOAD_CHUNK(c, stage) do {                                              \
        int ka = ((c) < 8) ? ((c) & 3) : ((c) - 4);                            \
        int kb = ((c) < 4) ? (c) : (((c) < 8) ? (c) : ((c) - 8));              \
        const char* asrc = arow + ka * 128 + lseg * 16;                        \
        const char* bsrc = brow + kb * 128 + lseg * 16;                        \
        uint32_t ad = sbase + (stage) * 32768 + dst_row;                       \
        uint32_t bd = ad + 16384;                                              \
        _Pragma("unroll")                                                      \
        for (int i = 0; i < 4; i++) {                                          \
            uint32_t so = (uint32_t)((lseg + i) * 16) ^ swz_st;                \
            asm volatile("cp.async.cg.shared.global [%0], [%1], 16;"           \
                         :: "r"(ad + so), "l"(asrc + i * 16) : "memory");      \
            asm volatile("cp.async.cg.shared.global [%0], [%1], 16;"           \
                         :: "r"(bd + so), "l"(bsrc + i * 16) : "memory");      \
        }                                                                      \
        asm volatile("cp.async.commit_group;" ::: "memory");                   \
    } while (0)

    LOAD_CHUNK(0, 0);
    LOAD_CHUNK(1, 1);

#pragma unroll
    for (int c = 0; c < NCH; c++) {
        if (c + 2 < NCH) {
            asm volatile("cp.async.wait_group 1;" ::: "memory");
            __syncthreads();
            LOAD_CHUNK(c + 2, (c + 2) % 3);
        } else {
            asm volatile("cp.async.wait_group 0;" ::: "memory");
            __syncthreads();
        }

        uint32_t stage_base = sbase + (uint32_t)((c % 3) * 32768);
#pragma unroll
        for (int kk = 0; kk < 4; kk++) {
            uint32_t af[4][4];
#pragma unroll
            for (int mi = 0; mi < 4; mi++) {
                asm volatile(
                    "ldmatrix.sync.aligned.m8n8.x4.shared.b16 {%0,%1,%2,%3}, [%4];"
                    : "=r"(af[mi][0]), "=r"(af[mi][1]),
                      "=r"(af[mi][2]), "=r"(af[mi][3])
                    : "r"(stage_base + a_off[kk] + mi * 2048));
            }
            uint32_t bf[4][2];
#pragma unroll
            for (int np = 0; np < 2; np++) {
                uint32_t r0, r1, r2, r3;
                asm volatile(
                    "ldmatrix.sync.aligned.m8n8.x4.shared.b16 {%0,%1,%2,%3}, [%4];"
                    : "=r"(r0), "=r"(r1), "=r"(r2), "=r"(r3)
                    : "r"(stage_base + b_off[kk] + np * 2048));
                bf[np * 2 + 0][0] = r0; bf[np * 2 + 0][1] = r1;
                bf[np * 2 + 1][0] = r2; bf[np * 2 + 1][1] = r3;
            }
#pragma unroll
            for (int mi = 0; mi < 4; mi++)
#pragma unroll
                for (int ni = 0; ni < 4; ni++) {
                    float* d = acc[mi * 4 + ni];
                    asm volatile(
                        "mma.sync.aligned.m16n8k16.row.col.f32.bf16.bf16.f32 "
                        "{%0,%1,%2,%3}, {%4,%5,%6,%7}, {%8,%9}, {%0,%1,%2,%3};"
                        : "+f"(d[0]), "+f"(d[1]), "+f"(d[2]), "+f"(d[3])
                        : "r"(af[mi][0]), "r"(af[mi][1]),
                          "r"(af[mi][2]), "r"(af[mi][3]),
                          "r"(bf[ni][0]), "r"(bf[ni][1]));
                }
        }
    }
#undef LOAD_CHUNK

#pragma unroll
    for (int mi = 0; mi < 4; mi++) {
#pragma unroll
        for (int ni = 0; ni < 4; ni++) {
            int r0 = bm + wm * 64 + mi * 16 + (lane >> 2);
            int c0 = bn + wn * 32 + ni * 8 + (lane & 3) * 2;
            float b0 = bias ? bias[c0] : 0.0f;
            float b1 = bias ? bias[c0 + 1] : 0.0f;
            float* d = acc[mi * 4 + ni];
            *(float2*)(C + (size_t)r0 * Nc + c0)
                = make_float2(d[0] + b0, d[1] + b1);
            *(float2*)(C + (size_t)(r0 + 8) * Nc + c0)
                = make_float2(d[2] + b0, d[3] + b1);
        }
    }
}

// ---------------- anchor attention per (b,h), 128 threads -----------------
__global__ __launch_bounds__(128) void attn_kernel(
    const float* __restrict__ qkv,
    const float* __restrict__ anc,
    const float* __restrict__ s,
    const float* __restrict__ logit_scale,
    __nv_bfloat16* __restrict__ out3,
    int square)
{
    int bh  = blockIdx.x;
    int b   = bh >> 3;
    int h   = bh & 7;
    int tid = threadIdx.x;
    int n   = tid >> 1;
    int g   = tid & 1;

    __shared__ __align__(16) float an_sh[NAa][Dd];
    __shared__ __align__(16) float sv_sh[Nt][Dd];
    __shared__ __align__(16) float a2_sh[Nt][NAa];
    __shared__ float att_sh[Nt][Nt + 1];
    __shared__ float rpb_sh[225];

    for (int i = tid; i < 225; i += 128) rpb_sh[i] = g_rpb[i * Hh + h];

    if (tid < NAa) {
        const float4* ap = (const float4*)(anc + ((size_t)(b * NAa + tid) * Cc + h * Dd));
        float ar[Dd];
        float ss = 0.0f;
#pragma unroll
        for (int d4 = 0; d4 < 8; d4++) {
            float4 av = ap[d4];
            ar[4*d4+0] = av.x; ar[4*d4+1] = av.y; ar[4*d4+2] = av.z; ar[4*d4+3] = av.w;
            ss += av.x*av.x + av.y*av.y + av.z*av.z + av.w*av.w;
        }
        float inv = 1.0f / fmaxf(sqrtf(ss), 1e-12f);
#pragma unroll
        for (int d = 0; d < Dd; d++) an_sh[tid][d] = ar[d] * inv;
    }

    const float4* q4 = (const float4*)(qkv + ((size_t)(b * Nt + n) * 768 + h * Dd + g * 16));
    const float4* k4 = q4 + 64;
    const float4* v4 = q4 + 128;
    const float4* s4 = (const float4*)(s + ((size_t)(b * Nt + n) * Cc + h * Dd + g * 16));
    float qr[16], kr[16];
    float qs = 0.0f, ks = 0.0f;
#pragma unroll
    for (int d4 = 0; d4 < 4; d4++) {
        float4 qv = q4[d4], kv = k4[d4], vv = v4[d4], sv = s4[d4];
        qr[4*d4+0] = qv.x; qr[4*d4+1] = qv.y; qr[4*d4+2] = qv.z; qr[4*d4+3] = qv.w;
        kr[4*d4+0] = kv.x; kr[4*d4+1] = kv.y; kr[4*d4+2] = kv.z; kr[4*d4+3] = kv.w;
        qs += qv.x*qv.x + qv.y*qv.y + qv.z*qv.z + qv.w*qv.w;
        ks += kv.x*kv.x + kv.y*kv.y + kv.z*kv.z + kv.w*kv.w;
        sv_sh[n][g*16 + 4*d4+0] = vv.x * sv.x;
        sv_sh[n][g*16 + 4*d4+1] = vv.y * sv.y;
        sv_sh[n][g*16 + 4*d4+2] = vv.z * sv.z;
        sv_sh[n][g*16 + 4*d4+3] = vv.w * sv.w;
    }
    qs += __shfl_xor_sync(0xFFFFFFFFu, qs, 1);
    ks += __shfl_xor_sync(0xFFFFFFFFu, ks, 1);
    float qin = 1.0f / fmaxf(sqrtf(qs), 1e-12f);
    float kin = 1.0f / fmaxf(sqrtf(ks), 1e-12f);
    __syncthreads();

    float a1[NAa];
    float s1v = 0.0f, s2v = 0.0f;
    float a2f[NAa];
#pragma unroll
    for (int m = 0; m < NAa; m++) {
        float p1 = 0.0f, p2 = 0.0f;
#pragma unroll
        for (int d = 0; d < 16; d++) {
            float av = an_sh[m][g*16 + d];
            p1 += qr[d] * av;
            p2 += kr[d] * av;
        }
        p1 += __shfl_xor_sync(0xFFFFFFFFu, p1, 1);
        p2 += __shfl_xor_sync(0xFFFFFFFFu, p2, 1);
        p1 *= qin; p2 *= kin;
        a1[m] = p1; a2f[m] = p2;
        s1v += p1 * p1; s2v += p2 * p2;
    }
    float i1n = 1.0f / fmaxf(sqrtf(s1v), 1e-12f);
    float i2n = 1.0f / fmaxf(sqrtf(s2v), 1e-12f);
#pragma unroll
    for (int m = 0; m < NAa; m++) a1[m] *= i1n;
    if (g == 0) {
#pragma unroll
        for (int m = 0; m < NAa; m++) a2_sh[n][m] = a2f[m] * i2n;
    }
    __syncthreads();

    float lsv = expf(fminf(logit_scale[h], LOG100));
    float scale = square ? (lsv * lsv) : lsv;
    int i1 = n >> 3, j1 = n & 7;
    float lv[32];
    float mx = -1e30f;
#pragma unroll
    for (int j = 0; j < 32; j++) {
        int k2 = g * 32 + j;
        const float4* a2v = (const float4*)(&a2_sh[k2][0]);
        float4 v0 = a2v[0], v1 = a2v[1], v2 = a2v[2], v3 = a2v[3];
        float accv = a1[0]*v0.x + a1[1]*v0.y + a1[2]*v0.z + a1[3]*v0.w
                   + a1[4]*v1.x + a1[5]*v1.y + a1[6]*v1.z + a1[7]*v1.w
                   + a1[8]*v2.x + a1[9]*v2.y + a1[10]*v2.z + a1[11]*v2.w
                   + a1[12]*v3.x + a1[13]*v3.y + a1[14]*v3.z + a1[15]*v3.w;
        int idx = (i1 - (k2 >> 3) + 7) * 15 + (j1 - (k2 & 7) + 7);
        float v = accv * scale + rpb_sh[idx];
        lv[j] = v;
        mx = fmaxf(mx, v);
    }
    mx = fmaxf(mx, __shfl_xor_sync(0xFFFFFFFFu, mx, 1));
    float sum = 0.0f;
#pragma unroll
    for (int j = 0; j < 32; j++) {
        float e = __expf(lv[j] - mx);
        att_sh[n][g * 32 + j] = e;
        sum += e;
    }
    sum += __shfl_xor_sync(0xFFFFFFFFu, sum, 1);
    float rinv = 1.0f / sum;
    __syncthreads();

    float oa[16];
#pragma unroll
    for (int d = 0; d < 16; d++) oa[d] = 0.0f;
    for (int k2 = 0; k2 < Nt; k2++) {
        float a = att_sh[n][k2];
        const float4* svp = (const float4*)&sv_sh[k2][g * 16];
#pragma unroll
        for (int d4 = 0; d4 < 4; d4++) {
            float4 v = svp[d4];
            oa[4*d4+0] += a * v.x;
            oa[4*d4+1] += a * v.y;
            oa[4*d4+2] += a * v.z;
            oa[4*d4+3] += a * v.w;
        }
    }
    __nv_bfloat16* orow = out3 + ((size_t)(b * Nt + n) * K2 + h * Dd + g * 16);
#pragma unroll
    for (int d = 0; d < 16; d += 2) {
        float o0v = oa[d] * rinv;
        float o1v = oa[d + 1] * rinv;
        __nv_bfloat16 h0 = __float2bfloat16(o0v);
        __nv_bfloat16 h1 = __float2bfloat16(o1v);
        __nv_bfloat16 l0 = __float2bfloat16(o0v - __bfloat162float(h0));
        __nv_bfloat16 l1 = __float2bfloat16(o1v - __bfloat162float(h1));
        *(__nv_bfloat162*)(orow + d)       = __halves2bfloat162(h0, h1);
        *(__nv_bfloat162*)(orow + 256 + d) = __halves2bfloat162(l0, l1);
    }
}

// ---------------- launch --------------------------------------------------
extern "C" void kernel_launch(void* const* d_in, const int* in_sizes, int n_in,
                              void* d_out, int out_size) {
    const float* m        = (const float*)d_in[0];
    const float* p        = (const float*)d_in[1];
    const float* m_l      = (const float*)d_in[2];
    const float* m_s      = (const float*)d_in[3];
    const float* p_l      = (const float*)d_in[4];
    const float* p_s      = (const float*)d_in[5];
    const float* m_qkv_w  = (const float*)d_in[6];
    const float* p_qkv_w  = (const float*)d_in[7];
    const float* m_q_bias = (const float*)d_in[8];
    const float* m_v_bias = (const float*)d_in[9];
    const float* p_q_bias = (const float*)d_in[10];
    const float* p_v_bias = (const float*)d_in[11];
    const float* m_ls     = (const float*)d_in[12];
    const float* p_ls     = (const float*)d_in[13];
    const float* cpb_w1   = (const float*)d_in[14];
    const float* cpb_b1   = (const float*)d_in[15];
    const float* cpb_w2   = (const float*)d_in[16];
    const float* m_anchor_w = (const float*)d_in[17];
    const float* p_anchor_w = (const float*)d_in[18];
    const float* m_proj_w = (const float*)d_in[19];
    const float* m_proj_b = (const float*)d_in[20];
    const float* p_proj_w = (const float*)d_in[21];
    const float* p_proj_b = (const float*)d_in[22];
    float* out = (float*)d_out;

    __nv_bfloat16 *a3m, *a3p, *al3m, *al3p, *w3qm, *w3qp, *w3am, *w3ap, *w3pm, *w3pp, *at3m, *at3p;
    float *qkvm, *qkvp, *ancm, *ancp, *biasm, *biasp;
    cudaGetSymbolAddress((void**)&a3m,  g_a3_m);
    cudaGetSymbolAddress((void**)&a3p,  g_a3_p);
    cudaGetSymbolAddress((void**)&al3m, g_al3_m);
    cudaGetSymbolAddress((void**)&al3p, g_al3_p);
    cudaGetSymbolAddress((void**)&w3qm, g_w3_qkv_m);
    cudaGetSymbolAddress((void**)&w3qp, g_w3_qkv_p);
    cudaGetSymbolAddress((void**)&w3am, g_w3_anc_m);
    cudaGetSymbolAddress((void**)&w3ap, g_w3_anc_p);
    cudaGetSymbolAddress((void**)&w3pm, g_w3_prj_m);
    cudaGetSymbolAddress((void**)&w3pp, g_w3_prj_p);
    cudaGetSymbolAddress((void**)&at3m, g_att3_m);
    cudaGetSymbolAddress((void**)&at3p, g_att3_p);
    cudaGetSymbolAddress((void**)&qkvm, g_qkv_m);
    cudaGetSymbolAddress((void**)&qkvp, g_qkv_p);
    cudaGetSymbolAddress((void**)&ancm, g_anc_m);
    cudaGetSymbolAddress((void**)&ancp, g_anc_p);
    cudaGetSymbolAddress((void**)&biasm, g_bias_m);
    cudaGetSymbolAddress((void**)&biasp, g_bias_p);

    const int SMEMSZ = 3 * 32768 + 1024;
    cudaFuncSetAttribute(gemm_mma, cudaFuncAttributeMaxDynamicSharedMemorySize, SMEMSZ);

    int MB = Bw * Nt;      // 65536
    int MA = Bw * NAa;     // 16384
    int PREP_M = AB + 195 + 4096 + 64 + 225;
    int PREP_P = AB + 195 + 4096 + 64;

    // #0: fused m-stream prep (incl. anchor convs + CPB)
    prep_full<<<PREP_M, 256>>>(m, m_qkv_w, m_q_bias, m_v_bias, m_l, m_anchor_w,
                               a3m, w3qm, biasm, al3m, w3am,
                               cpb_w1, cpb_b1, cpb_w2);
    // #1: anchor GEMM m
    gemm_mma<<<dim3(2, MA / 128), 256, SMEMSZ>>>(al3m, w3am, nullptr, ancm, MA, 256);
    // #2: QKV GEMM m
    gemm_mma<<<dim3(6, MB / 128), 256, SMEMSZ>>>(a3m, w3qm, biasm, qkvm, MB, 768);
    // #3: attention m  <-- ncu capture target
    attn_kernel<<<Bw * Hh, 128>>>(qkvm, ancm, m_s, m_ls, at3m, 0);

    // p stream
    prep_full<<<PREP_P, 256>>>(p, p_qkv_w, p_q_bias, p_v_bias, p_l, p_anchor_w,
                               a3p, w3qp, biasp, al3p, w3ap,
                               nullptr, nullptr, nullptr);
    gemm_mma<<<dim3(2, MA / 128), 256, SMEMSZ>>>(al3p, w3ap, nullptr, ancp, MA, 256);
    gemm_mma<<<dim3(6, MB / 128), 256, SMEMSZ>>>(a3p, w3qp, biasp, qkvp, MB, 768);
    attn_kernel<<<Bw * Hh, 128>>>(qkvp, ancp, p_s, p_ls, at3p, 1);

    // proj weight convs (both streams, one launch) + proj GEMMs
    conv_proj_dual<<<128, 256>>>(m_proj_w, p_proj_w, w3pm, w3pp);
    gemm_mma<<<dim3(2, MB / 128), 256, SMEMSZ>>>(at3m, w3pm, m_proj_b, out, MB, 256);
    gemm_mma<<<dim3(2, MB / 128), 256, SMEMSZ>>>(at3p, w3pp, p_proj_b,
                                                 out + (size_t)MB * Cc, MB, 256);
}